// round 3
// baseline (speedup 1.0000x reference)
#include <cuda_runtime.h>
#include <math.h>

#define Bsz 4
#define Cch 192
#define Hh 56
#define Ww 56
#define HW (Hh*Ww)
#define NS 27

// scratch (static device globals; no allocation)
__device__ float g_xt [Bsz*HW*Cch];   // x transposed to [b][n][c]  (NHWC)
__device__ float g_att[Bsz*HW*Cch];   // attention output, [b][n][c]

// ---------------------------------------------------------------------------
// Kernel 1: NCHW -> NHWC transpose (per-batch CxHW matrix transpose)
// ---------------------------------------------------------------------------
__global__ __launch_bounds__(256) void transpose_k(const float* __restrict__ x)
{
    __shared__ float tile[32][33];
    const int n0 = blockIdx.x << 5;      // HW tile (3136 = 98*32)
    const int c0 = blockIdx.y << 5;      // C tile  (192  = 6*32)
    const int b  = blockIdx.z;
    const int tx = threadIdx.x, ty = threadIdx.y;   // (32, 8)
    const float* xb = x + (size_t)b * Cch * HW;
#pragma unroll
    for (int i = 0; i < 4; i++)
        tile[ty + i*8][tx] = xb[(size_t)(c0 + ty + i*8) * HW + n0 + tx];
    __syncthreads();
    float* dst = g_xt + (size_t)b * HW * Cch;
#pragma unroll
    for (int i = 0; i < 4; i++)
        dst[(size_t)(n0 + ty + i*8) * Cch + c0 + tx] = tile[tx][ty + i*8];
}

// ---------------------------------------------------------------------------
// Kernel 2: shift-attention. One block per (b,h,w); thread = channel.
// tanh with a SINGLE MUFU (EX2); the reciprocal of d=1+e (narrow range [1,2])
// is a quadratic init + 2 Newton steps on the FMA pipe. rel err ~5e-6.
// ---------------------------------------------------------------------------
__device__ __forceinline__ float fast_tanh(float p)
{
    float a = fminf(fabsf(p), 9.0f);          // tanh(9)=1-2.5e-8
    float e = __expf(-2.0f * a);              // 1 MUFU.EX2, e in [1.5e-8, 1]
    float d = 1.0f + e;                       // [1, 2]
    float y = 2.166667f + d * (-1.5f + d * 0.3333333f);  // ~1/d, err<5e-2
    y = y * (2.0f - d * y);                   // err ~2.3e-3
    y = y * (2.0f - d * y);                   // err ~5e-6
    float t = (1.0f - e) * y;
    return copysignf(t, p);
}

__global__ __launch_bounds__(192) void att_k()
{
    const int w = blockIdx.x, h = blockIdx.y, b = blockIdx.z;
    const int c = threadIdx.x;                         // 192 threads = channels
    __shared__ float ts[192 * 29];                     // per-(c,shift) tanh (stride 29: conflict-free)
    __shared__ float pr[6 * NS];                       // per-group partial scores
    __shared__ float wgt[NS];
    const float scale = 0.19245008972987526f;          // 27^-0.5
    const float* base = g_xt + (size_t)b * HW * Cch;

    const float xc = base[(h*Ww + w)*Cch + c];
    float xs[NS];
#pragma unroll
    for (int i = 0; i < 14; i++) {                     // h-shifts 0,4,...,52
        int hh = h - 4*i; if (hh < 0) hh += Hh;
        xs[i] = base[(hh*Ww + w)*Cch + c];
    }
#pragma unroll
    for (int j = 1; j < 14; j++) {                     // w-shifts 4,...,52
        int ww = w - 4*j; if (ww < 0) ww += Ww;
        xs[13 + j] = base[(h*Ww + ww)*Cch + c];
    }

#pragma unroll
    for (int i = 0; i < NS; i++)
        ts[c*29 + i] = fast_tanh(scale * xc * xs[i]);
    __syncthreads();

    // parallel score reduction: 162 threads = 27 shifts x 6 channel-groups
    if (c < 162) {
        const int i = c % NS, g = c / NS;
        const int cb = g * 32;
        float s0 = 0.f, s1 = 0.f;
#pragma unroll
        for (int cc = 0; cc < 32; cc += 2) {
            s0 += ts[(cb + cc    )*29 + i];
            s1 += ts[(cb + cc + 1)*29 + i];
        }
        pr[g*NS + i] = s0 + s1;
    }
    __syncthreads();

    // warp 0: combine 6 partials, softmax over 27 shifts
    if (c < 32) {
        float s = 0.f;
        if (c < NS) {
#pragma unroll
            for (int g = 0; g < 6; g++) s += pr[g*NS + c];
        }
        float sv = (c < NS) ? s : -1e30f;
#pragma unroll
        for (int off = 16; off; off >>= 1)
            sv = fmaxf(sv, __shfl_xor_sync(0xffffffffu, sv, off));
        float e = (c < NS) ? __expf(s - sv) : 0.f;
        float tot = e;
#pragma unroll
        for (int off = 16; off; off >>= 1)
            tot += __shfl_xor_sync(0xffffffffu, tot, off);
        if (c < NS) wgt[c] = __fdividef(e, tot);
    }
    __syncthreads();

    float o = 0.f;
#pragma unroll
    for (int i = 0; i < NS; i++) o = fmaf(wgt[i], xs[i], o);
    g_att[(size_t)b*HW*Cch + (h*Ww + w)*Cch + c] = o;
}

// ---------------------------------------------------------------------------
// Kernel 3: 1x1 conv as GEMM (M=192, N=3136/batch, K=384) + bias + BN + GELU.
// Packed f32x2 FFMA2 inner loop. BN=32 -> 392 blocks (was 196) to kill the
// 1.3-wave quantization loss on 148 SMs.
// ---------------------------------------------------------------------------
#define BN 32
#define BK 32
#define WS_STRIDE 194   // even (8B-aligned 64-bit reads)
#define CS_STRIDE 33

__device__ __forceinline__ unsigned long long dup2(float v)
{
    unsigned long long d; unsigned r = __float_as_uint(v);
    asm("mov.b64 %0, {%1, %1};" : "=l"(d) : "r"(r));
    return d;
}
#define FFMA2(d, a, b) asm("fma.rn.f32x2 %0, %1, %2, %0;" : "+l"(d) : "l"(a), "l"(b))

__global__ __launch_bounds__(256) void gemm_k(
    const float* __restrict__ cw,    // conv_w [192][384]
    const float* __restrict__ bias,
    const float* __restrict__ gamma,
    const float* __restrict__ beta,
    const float* __restrict__ mean,
    const float* __restrict__ var,
    float* __restrict__ out)         // [b][o][n] (NCHW)
{
    __shared__ float wS[BK * WS_STRIDE];   // [k][o]
    __shared__ float catS[BK * CS_STRIDE]; // [k][n]
    const int b  = blockIdx.y;
    const int n0 = blockIdx.x * BN;
    const int t  = threadIdx.x;
    const int tn = t & 15;                 // 16 n-groups of 2
    const int tm = t >> 4;                 // 16 o-groups of 12

    unsigned long long acc[6][2];          // 6 o-pairs x 2 n
#pragma unroll
    for (int p = 0; p < 6; p++)
#pragma unroll
        for (int nn = 0; nn < 2; nn++) acc[p][nn] = 0ULL;

    const float* xb = g_xt  + (size_t)b * HW * Cch;
    const float* ab = g_att + (size_t)b * HW * Cch;

    for (int kc = 0; kc < 2*Cch; kc += BK) {
        const float* src  = (kc < Cch) ? xb : ab;
        const int   cbase = (kc < Cch) ? kc : (kc - Cch);
        __syncthreads();
        // cat tile: 32 c x 32 n (lanes along c, coalesced in NHWC)
#pragma unroll
        for (int s = 0; s < 4; s++) {
            int f = t + 256*s;
            int cc = f & 31, j = f >> 5;
            catS[cc*CS_STRIDE + j] = src[(size_t)(n0 + j)*Cch + cbase + cc];
        }
        // weight tile: 32 c x 192 o, transposed into [k][o]
#pragma unroll
        for (int s = 0; s < 24; s++) {
            int f = t + 256*s;
            int cc = f & 31, o = f >> 5;
            wS[cc*WS_STRIDE + o] = cw[o*384 + kc + cc];
        }
        __syncthreads();
#pragma unroll
        for (int k = 0; k < BK; k++) {
            unsigned long long a[6];
#pragma unroll
            for (int p = 0; p < 6; p++)
                a[p] = *reinterpret_cast<const unsigned long long*>(
                           &wS[k*WS_STRIDE + tm*12 + 2*p]);
            unsigned long long bb[2];
#pragma unroll
            for (int nn = 0; nn < 2; nn++)
                bb[nn] = dup2(catS[k*CS_STRIDE + tn*2 + nn]);
#pragma unroll
            for (int p = 0; p < 6; p++)
#pragma unroll
                for (int nn = 0; nn < 2; nn++)
                    FFMA2(acc[p][nn], a[p], bb[nn]);
        }
    }

    // epilogue: bias + BN(eval) + exact GELU, float2 stores
#pragma unroll
    for (int p = 0; p < 6; p++) {
        float yv[2][2];
#pragma unroll
        for (int nn = 0; nn < 2; nn++) {
            unsigned long long v = acc[p][nn];
            yv[0][nn] = __uint_as_float((unsigned)v);
            yv[1][nn] = __uint_as_float((unsigned)(v >> 32));
        }
#pragma unroll
        for (int q = 0; q < 2; q++) {
            int o = tm*12 + 2*p + q;
            float bi  = bias[o];
            float inv = gamma[o] * rsqrtf(var[o] + 1e-5f);
            float mu  = mean[o], bt = beta[o];
            float2 r;
#pragma unroll
            for (int nn = 0; nn < 2; nn++) {
                float y = (yv[q][nn] + bi - mu) * inv + bt;
                ((float*)&r)[nn] = 0.5f * y * (1.0f + erff(y * 0.70710678118654752f));
            }
            *reinterpret_cast<float2*>(
                &out[(size_t)(b*Cch + o)*HW + n0 + tn*2]) = r;
        }
    }
}

// ---------------------------------------------------------------------------
extern "C" void kernel_launch(void* const* d_in, const int* in_sizes, int n_in,
                              void* d_out, int out_size)
{
    const float* x     = (const float*)d_in[0];
    const float* cw    = (const float*)d_in[1];
    const float* cb    = (const float*)d_in[2];
    const float* gamma = (const float*)d_in[3];
    const float* beta  = (const float*)d_in[4];
    const float* mean  = (const float*)d_in[5];
    const float* var   = (const float*)d_in[6];
    float* out = (float*)d_out;

    transpose_k<<<dim3(HW/32, Cch/32, Bsz), dim3(32, 8)>>>(x);
    att_k<<<dim3(Ww, Hh, Bsz), 192>>>();
    gemm_k<<<dim3(HW/BN, Bsz), 256>>>(cw, cb, gamma, beta, mean, var, out);
}

// round 4
// speedup vs baseline: 1.1513x; 1.1513x over previous
#include <cuda_runtime.h>
#include <math.h>

#define Bsz 4
#define Cch 192
#define Hh 56
#define Ww 56
#define HW (Hh*Ww)

// scratch (static device globals; no allocation)
__device__ float g_xt [Bsz*HW*Cch];   // x transposed to [b][n][c]  (NHWC)
__device__ float g_att[Bsz*HW*Cch];   // attention output, [b][n][c]
__device__ float g_sc [Bsz*HW*32];    // scores, padded row of 32 (cols 0..26 used)

// ---------------------------------------------------------------------------
// Kernel 1: NCHW -> NHWC transpose
// ---------------------------------------------------------------------------
__global__ __launch_bounds__(256) void transpose_k(const float* __restrict__ x)
{
    __shared__ float tile[32][33];
    const int n0 = blockIdx.x << 5;
    const int c0 = blockIdx.y << 5;
    const int b  = blockIdx.z;
    const int tx = threadIdx.x, ty = threadIdx.y;
    const float* xb = x + (size_t)b * Cch * HW;
#pragma unroll
    for (int i = 0; i < 4; i++)
        tile[ty + i*8][tx] = xb[(size_t)(c0 + ty + i*8) * HW + n0 + tx];
    __syncthreads();
    float* dst = g_xt + (size_t)b * HW * Cch;
#pragma unroll
    for (int i = 0; i < 4; i++)
        dst[(size_t)(n0 + ty + i*8) * Cch + c0 + tx] = tile[tx][ty + i*8];
}

// ---------------------------------------------------------------------------
// tanh via 2 MUFU (EX2 + RCP): 16 MUFU-cyc/warp beats Newton's 26 FMA-cyc.
// ---------------------------------------------------------------------------
__device__ __forceinline__ float fast_tanh(float p)
{
    float e = __expf(-2.0f * fabsf(p));
    float t = __fdividef(1.0f - e, 1.0f + e);
    return copysignf(t, p);
}

// ---------------------------------------------------------------------------
// Kernel 2: ring pair-score kernel. Block = one 14-ring (h-ring mode0 along
// h for fixed (w, h%4); w-ring mode1). Each unordered pair (i,j) serves score
// entries (i, i-j) and (j, j-i)  ->  tanh count halved.
// ---------------------------------------------------------------------------
#define TS_STRIDE 193   // bank(p,c) = (p+c)%32 -> conflict-free rows

template<int LO, int HI, int MODE>
__device__ __forceinline__ void score_compute(const float* sxr, const float* xr,
                                              float* ts, int c)
{
    int p = 0;
#pragma unroll
    for (int i = 0; i < 14; i++)
#pragma unroll
        for (int j = (MODE ? i + 1 : i); j < 14; j++) {
            if (p >= LO && p < HI)
                ts[(p - LO)*TS_STRIDE + c] = fast_tanh(sxr[i] * xr[j]);
            p++;
        }
}

__device__ __forceinline__ void reduce_rows(const float* ts, float* redS,
                                            int c, int nrows, int base)
{
    if (c < nrows) {
        const float* row = ts + c*TS_STRIDE;
        float s0=0.f, s1=0.f, s2=0.f, s3=0.f;
#pragma unroll 8
        for (int cc = 0; cc < 192; cc += 4) {
            s0 += row[cc]; s1 += row[cc+1]; s2 += row[cc+2]; s3 += row[cc+3];
        }
        redS[base + c] = (s0 + s1) + (s2 + s3);
    }
}

__global__ __launch_bounds__(192) void score_k()
{
    __shared__ float ts[53 * TS_STRIDE];   // 40.9KB
    __shared__ float redS[105];
    const int x = blockIdx.x;              // w (mode0) or h (mode1)
    const int r = blockIdx.y;              // residue 0..3
    const int b = blockIdx.z >> 1, mode = blockIdx.z & 1;
    const int c = threadIdx.x;
    const float* base = g_xt + (size_t)b * HW * Cch;

    float xr[14], sxr[14];
#pragma unroll
    for (int a = 0; a < 14; a++) {
        int n = mode ? (x*Ww + r + 4*a) : ((r + 4*a)*Ww + x);
        xr[a]  = base[n*Cch + c];
        sxr[a] = xr[a] * 0.19245008972987526f;   // 27^-0.5
    }
    const int NP = mode ? 91 : 105;

    if (mode == 0) score_compute<0,53,0>(sxr, xr, ts, c);
    else           score_compute<0,53,1>(sxr, xr, ts, c);
    __syncthreads();
    reduce_rows(ts, redS, c, 53, 0);
    __syncthreads();
    if (mode == 0) score_compute<53,105,0>(sxr, xr, ts, c);
    else           score_compute<53,91,1>(sxr, xr, ts, c);
    __syncthreads();
    reduce_rows(ts, redS, c, NP - 53, 53);
    __syncthreads();

    // scatter: each (position a, shift) entry maps to exactly one pair
    float* scb = g_sc + (size_t)b * HW * 32;
    if (mode == 0) {
        for (int e = c; e < 196; e += 192) {        // 14 pos x 14 h-shifts
            int a = e / 14, k = e % 14;
            int j = a - k; if (j < 0) j += 14;
            int lo = min(a, j), hi = max(a, j);
            int id = lo*14 - (lo*(lo-1))/2 + (hi - lo);   // upper-incl-diag index
            int n = (r + 4*a)*Ww + x;
            scb[n*32 + k] = redS[id];
        }
    } else {
        for (int e = c; e < 182; e += 192) {        // 14 pos x 13 w-shifts
            int a = e / 13, m = e % 13 + 1;
            int j = a - m; if (j < 0) j += 14;
            int lo = min(a, j), hi = max(a, j);
            int id = lo*13 - (lo*(lo-1))/2 + (hi - lo - 1); // strict-upper index
            int n = x*Ww + r + 4*a;
            scb[n*32 + 13 + m] = redS[id];
        }
    }
}

// ---------------------------------------------------------------------------
// Kernel 3: ring weighted-sum. Per ring: softmax (full 27) for its 14
// positions, then out[a] = sum_k wgt[a][k] * xr[(a-k)%14].
// mode0 (h) writes g_att; mode1 (w) accumulates. Launched sequentially.
// ---------------------------------------------------------------------------
__global__ __launch_bounds__(192) void sum_k(int mode)
{
    __shared__ float wgt[14*14];
    const int x = blockIdx.x, r = blockIdx.y, b = blockIdx.z;
    const int c = threadIdx.x;
    const float* base = g_xt + (size_t)b * HW * Cch;
    float* attb = g_att + (size_t)b * HW * Cch;
    const float* scb = g_sc + (size_t)b * HW * 32;

    if (c < 14) {                                // thread = one ring position
        int n = mode ? (x*Ww + r + 4*c) : ((r + 4*c)*Ww + x);
        const float* srow = scb + n*32;
        float s[27], mx = -1e30f;
#pragma unroll
        for (int k = 0; k < 27; k++) { s[k] = srow[k]; mx = fmaxf(mx, s[k]); }
        float tot = 0.f;
#pragma unroll
        for (int k = 0; k < 27; k++) { s[k] = __expf(s[k] - mx); tot += s[k]; }
        float inv = __fdividef(1.f, tot);
        if (mode == 0) {
#pragma unroll
            for (int k = 0; k < 14; k++) wgt[c*14 + k] = s[k] * inv;
        } else {
#pragma unroll
            for (int m = 1; m < 14; m++) wgt[c*14 + m-1] = s[13 + m] * inv;
        }
    }
    __syncthreads();

    float xr[14];
#pragma unroll
    for (int a = 0; a < 14; a++) {
        int n = mode ? (x*Ww + r + 4*a) : ((r + 4*a)*Ww + x);
        xr[a] = base[n*Cch + c];
    }
#pragma unroll
    for (int a = 0; a < 14; a++) {
        int n = mode ? (x*Ww + r + 4*a) : ((r + 4*a)*Ww + x);
        if (mode == 0) {
            float o = 0.f;
#pragma unroll
            for (int k = 0; k < 14; k++) {
                int j = (a - k + 14) % 14;          // compile-time
                o = fmaf(wgt[a*14 + k], xr[j], o);
            }
            attb[n*Cch + c] = o;
        } else {
            float o = attb[n*Cch + c];
#pragma unroll
            for (int m = 1; m < 14; m++) {
                int j = (a - m + 14) % 14;
                o = fmaf(wgt[a*14 + m-1], xr[j], o);
            }
            attb[n*Cch + c] = o;
        }
    }
}

// ---------------------------------------------------------------------------
// Kernel 4: GEMM (M=192, N=3136/b, K=384) + bias + BN + GELU, FFMA2 inner
// loop. catS pre-duplicated in smem (drops 2 dup-movs/k), weights LDG.128.
// ---------------------------------------------------------------------------
#define BN 32
#define BK 32
#define WS_STRIDE 194
#define CS2 66

#define FFMA2(d, a, b) asm("fma.rn.f32x2 %0, %1, %2, %0;" : "+l"(d) : "l"(a), "l"(b))

__global__ __launch_bounds__(256) void gemm_k(
    const float* __restrict__ cw,
    const float* __restrict__ bias,
    const float* __restrict__ gamma,
    const float* __restrict__ beta,
    const float* __restrict__ mean,
    const float* __restrict__ var,
    float* __restrict__ out)
{
    __shared__ float wS[BK * WS_STRIDE];    // [k][o]
    __shared__ float catS[BK * CS2];        // [k][n] duplicated pairs
    const int b  = blockIdx.y;
    const int n0 = blockIdx.x * BN;
    const int t  = threadIdx.x;
    const int tn = t & 15;                  // 16 n-groups of 2
    const int tm = t >> 4;                  // 16 o-groups of 12

    unsigned long long acc[6][2];
#pragma unroll
    for (int p = 0; p < 6; p++)
#pragma unroll
        for (int nn = 0; nn < 2; nn++) acc[p][nn] = 0ULL;

    const float* xb = g_xt  + (size_t)b * HW * Cch;
    const float* ab = g_att + (size_t)b * HW * Cch;

    for (int kc = 0; kc < 2*Cch; kc += BK) {
        const float* src  = (kc < Cch) ? xb : ab;
        const int   cbase = (kc < Cch) ? kc : (kc - Cch);
        __syncthreads();
#pragma unroll
        for (int s = 0; s < 4; s++) {       // cat tile, duplicated store
            int f = t + 256*s;
            int cc = f & 31, j = f >> 5;
            float v = src[(size_t)(n0 + j)*Cch + cbase + cc];
            *reinterpret_cast<float2*>(&catS[cc*CS2 + 2*j]) = make_float2(v, v);
        }
#pragma unroll
        for (int s = 0; s < 6; s++) {       // weight tile via LDG.128
            int f = t + 256*s;              // 0..1535
            int cc4 = (f & 7)*4, o = f >> 3;
            float4 v = *reinterpret_cast<const float4*>(&cw[o*384 + kc + cc4]);
            wS[(cc4+0)*WS_STRIDE + o] = v.x;
            wS[(cc4+1)*WS_STRIDE + o] = v.y;
            wS[(cc4+2)*WS_STRIDE + o] = v.z;
            wS[(cc4+3)*WS_STRIDE + o] = v.w;
        }
        __syncthreads();
#pragma unroll
        for (int k = 0; k < BK; k++) {
            unsigned long long a[6], bb[2];
#pragma unroll
            for (int p = 0; p < 6; p++)
                a[p] = *reinterpret_cast<const unsigned long long*>(
                           &wS[k*WS_STRIDE + tm*12 + 2*p]);
            bb[0] = *reinterpret_cast<const unsigned long long*>(&catS[k*CS2 + 4*tn]);
            bb[1] = *reinterpret_cast<const unsigned long long*>(&catS[k*CS2 + 4*tn + 2]);
#pragma unroll
            for (int p = 0; p < 6; p++)
#pragma unroll
                for (int nn = 0; nn < 2; nn++)
                    FFMA2(acc[p][nn], a[p], bb[nn]);
        }
    }

#pragma unroll
    for (int p = 0; p < 6; p++) {
        float yv[2][2];
#pragma unroll
        for (int nn = 0; nn < 2; nn++) {
            unsigned long long v = acc[p][nn];
            yv[0][nn] = __uint_as_float((unsigned)v);
            yv[1][nn] = __uint_as_float((unsigned)(v >> 32));
        }
#pragma unroll
        for (int q = 0; q < 2; q++) {
            int o = tm*12 + 2*p + q;
            float bi  = bias[o];
            float inv = gamma[o] * rsqrtf(var[o] + 1e-5f);
            float mu  = mean[o], bt = beta[o];
            float2 rr;
#pragma unroll
            for (int nn = 0; nn < 2; nn++) {
                float y = (yv[q][nn] + bi - mu) * inv + bt;
                ((float*)&rr)[nn] = 0.5f * y * (1.0f + erff(y * 0.70710678118654752f));
            }
            *reinterpret_cast<float2*>(
                &out[(size_t)(b*Cch + o)*HW + n0 + tn*2]) = rr;
        }
    }
}

// ---------------------------------------------------------------------------
extern "C" void kernel_launch(void* const* d_in, const int* in_sizes, int n_in,
                              void* d_out, int out_size)
{
    const float* x     = (const float*)d_in[0];
    const float* cw    = (const float*)d_in[1];
    const float* cb    = (const float*)d_in[2];
    const float* gamma = (const float*)d_in[3];
    const float* beta  = (const float*)d_in[4];
    const float* mean  = (const float*)d_in[5];
    const float* var   = (const float*)d_in[6];
    float* out = (float*)d_out;

    transpose_k<<<dim3(HW/32, Cch/32, Bsz), dim3(32, 8)>>>(x);
    score_k<<<dim3(56, 4, 2*Bsz), 192>>>();
    sum_k<<<dim3(56, 4, Bsz), 192>>>(0);
    sum_k<<<dim3(56, 4, Bsz), 192>>>(1);
    gemm_k<<<dim3(HW/BN, Bsz), 256>>>(cw, cb, gamma, beta, mean, var, out);
}